// round 1
// baseline (speedup 1.0000x reference)
#include <cuda_runtime.h>
#include <cuda_bf16.h>
#include <math_constants.h>

// Problem shape: B=4, H=16, L=2048, D=64 (fp32)
#define BHN 64
#define LL  2048
#define DD  64

static const size_t CTX_ELEMS = (size_t)BHN * LL * DD;          // 8,388,608
static const size_t ATT_ELEMS = (size_t)BHN * LL * (size_t)LL;  // 268,435,456

// ---------------------------------------------------------------------------
// K1: S[bh, i, j] = sum_d Q[bh,i,d] * K[bh,j,d]
// 128x128 tile per CTA, 256 threads, 8x8 per thread, K-chunks of 16.
// ---------------------------------------------------------------------------
__global__ __launch_bounds__(256) void qk_kernel(const float* __restrict__ Q,
                                                 const float* __restrict__ K,
                                                 float* __restrict__ S) {
    __shared__ float Qs[16][128];
    __shared__ float Ks[16][128];

    const int bh = blockIdx.z;
    const float* Qb = Q + (size_t)bh * LL * DD;
    const float* Kb = K + (size_t)bh * LL * DD;
    float* Sb = S + (size_t)bh * LL * (size_t)LL;

    const int tileM = blockIdx.y * 128;
    const int tileN = blockIdx.x * 128;
    const int tid = threadIdx.x;
    const int tm = (tid >> 4) << 3;   // 0..120
    const int tn = (tid & 15) << 3;   // 0..120

    float acc[8][8];
#pragma unroll
    for (int i = 0; i < 8; i++)
#pragma unroll
        for (int j = 0; j < 8; j++) acc[i][j] = 0.f;

    for (int k0 = 0; k0 < DD; k0 += 16) {
        // Load 128x16 of Q and K (transposed into [k][m] layout in smem).
#pragma unroll
        for (int i = 0; i < 2; i++) {
            int idx = tid * 2 + i;           // 0..511
            int r = idx >> 2;                // 0..127
            int c = (idx & 3) << 2;          // 0,4,8,12
            float4 v = *reinterpret_cast<const float4*>(Qb + (size_t)(tileM + r) * DD + k0 + c);
            Qs[c + 0][r] = v.x; Qs[c + 1][r] = v.y; Qs[c + 2][r] = v.z; Qs[c + 3][r] = v.w;
            float4 w = *reinterpret_cast<const float4*>(Kb + (size_t)(tileN + r) * DD + k0 + c);
            Ks[c + 0][r] = w.x; Ks[c + 1][r] = w.y; Ks[c + 2][r] = w.z; Ks[c + 3][r] = w.w;
        }
        __syncthreads();

#pragma unroll
        for (int dk = 0; dk < 16; dk++) {
            float a[8], b[8];
#pragma unroll
            for (int i = 0; i < 8; i++) a[i] = Qs[dk][tm + i];
#pragma unroll
            for (int j = 0; j < 8; j++) b[j] = Ks[dk][tn + j];
#pragma unroll
            for (int i = 0; i < 8; i++)
#pragma unroll
                for (int j = 0; j < 8; j++)
                    acc[i][j] = fmaf(a[i], b[j], acc[i][j]);
        }
        __syncthreads();
    }

#pragma unroll
    for (int i = 0; i < 8; i++) {
        size_t off = (size_t)(tileM + tm + i) * LL + tileN + tn;
        *reinterpret_cast<float4*>(Sb + off)     = make_float4(acc[i][0], acc[i][1], acc[i][2], acc[i][3]);
        *reinterpret_cast<float4*>(Sb + off + 4) = make_float4(acc[i][4], acc[i][5], acc[i][6], acc[i][7]);
    }
}

// ---------------------------------------------------------------------------
// K2: in-place row softmax. One CTA (256 threads) per row of 2048 floats.
// ---------------------------------------------------------------------------
__global__ __launch_bounds__(256) void softmax_kernel(float* __restrict__ S) {
    __shared__ float wred[8];
    __shared__ float bcast;

    float* p = S + (size_t)blockIdx.x * LL;
    const int tid = threadIdx.x;
    const int warp = tid >> 5, lane = tid & 31;

    float4 v0 = reinterpret_cast<const float4*>(p)[tid * 2];
    float4 v1 = reinterpret_cast<const float4*>(p)[tid * 2 + 1];
    float vals[8] = {v0.x, v0.y, v0.z, v0.w, v1.x, v1.y, v1.z, v1.w};

    // max
    float m = vals[0];
#pragma unroll
    for (int i = 1; i < 8; i++) m = fmaxf(m, vals[i]);
#pragma unroll
    for (int o = 16; o > 0; o >>= 1) m = fmaxf(m, __shfl_xor_sync(0xffffffffu, m, o));
    if (lane == 0) wred[warp] = m;
    __syncthreads();
    if (warp == 0) {
        float x = (lane < 8) ? wred[lane] : -CUDART_INF_F;
#pragma unroll
        for (int o = 4; o > 0; o >>= 1) x = fmaxf(x, __shfl_xor_sync(0xffffffffu, x, o));
        if (lane == 0) bcast = x;
    }
    __syncthreads();
    m = bcast;

    // sum of exp
    float e[8];
    float s = 0.f;
#pragma unroll
    for (int i = 0; i < 8; i++) { e[i] = __expf(vals[i] - m); s += e[i]; }
#pragma unroll
    for (int o = 16; o > 0; o >>= 1) s += __shfl_xor_sync(0xffffffffu, s, o);
    __syncthreads();               // protect wred reuse
    if (lane == 0) wred[warp] = s;
    __syncthreads();
    if (warp == 0) {
        float x = (lane < 8) ? wred[lane] : 0.f;
#pragma unroll
        for (int o = 4; o > 0; o >>= 1) x += __shfl_xor_sync(0xffffffffu, x, o);
        if (lane == 0) bcast = 1.f / x;
    }
    __syncthreads();
    const float inv = bcast;

    float4 o0 = make_float4(e[0] * inv, e[1] * inv, e[2] * inv, e[3] * inv);
    float4 o1 = make_float4(e[4] * inv, e[5] * inv, e[6] * inv, e[7] * inv);
    reinterpret_cast<float4*>(p)[tid * 2]     = o0;
    reinterpret_cast<float4*>(p)[tid * 2 + 1] = o1;
}

// ---------------------------------------------------------------------------
// K3: O[bh,:,:] = P[bh,:,:] @ V[bh,:,:]  (M=2048, N=64, K=2048)
// 128x64 tile per CTA, 256 threads, 8x4 per thread, K-chunks of 16.
// ---------------------------------------------------------------------------
__global__ __launch_bounds__(256) void pv_kernel(const float* __restrict__ P,
                                                 const float* __restrict__ V,
                                                 float* __restrict__ O) {
    __shared__ float Ps[16][128];
    __shared__ float Vs[16][64];

    const int bh = blockIdx.z;
    const float* Pb = P + (size_t)bh * LL * (size_t)LL;
    const float* Vb = V + (size_t)bh * LL * DD;
    float* Ob = O + (size_t)bh * LL * DD;

    const int tileM = blockIdx.y * 128;
    const int tid = threadIdx.x;
    const int tm = (tid >> 4) << 3;  // 0..120
    const int tn = (tid & 15) << 2;  // 0..60

    float acc[8][4];
#pragma unroll
    for (int i = 0; i < 8; i++)
#pragma unroll
        for (int j = 0; j < 4; j++) acc[i][j] = 0.f;

    for (int k0 = 0; k0 < LL; k0 += 16) {
        // P tile: 128 rows x 16 k
#pragma unroll
        for (int i = 0; i < 2; i++) {
            int idx = tid * 2 + i;
            int r = idx >> 2;
            int c = (idx & 3) << 2;
            float4 v = *reinterpret_cast<const float4*>(Pb + (size_t)(tileM + r) * LL + k0 + c);
            Ps[c + 0][r] = v.x; Ps[c + 1][r] = v.y; Ps[c + 2][r] = v.z; Ps[c + 3][r] = v.w;
        }
        // V tile: 16 k x 64 d
        {
            int r = tid >> 4;          // 0..15
            int c = (tid & 15) << 2;   // 0..60
            float4 v = *reinterpret_cast<const float4*>(Vb + (size_t)(k0 + r) * DD + c);
            *reinterpret_cast<float4*>(&Vs[r][c]) = v;
        }
        __syncthreads();

#pragma unroll
        for (int dk = 0; dk < 16; dk++) {
            float a[8], b[4];
#pragma unroll
            for (int i = 0; i < 8; i++) a[i] = Ps[dk][tm + i];
#pragma unroll
            for (int j = 0; j < 4; j++) b[j] = Vs[dk][tn + j];
#pragma unroll
            for (int i = 0; i < 8; i++)
#pragma unroll
                for (int j = 0; j < 4; j++)
                    acc[i][j] = fmaf(a[i], b[j], acc[i][j]);
        }
        __syncthreads();
    }

#pragma unroll
    for (int i = 0; i < 8; i++) {
        *reinterpret_cast<float4*>(Ob + (size_t)(tileM + tm + i) * DD + tn) =
            make_float4(acc[i][0], acc[i][1], acc[i][2], acc[i][3]);
    }
}

// ---------------------------------------------------------------------------
// Fallback (context-only output): fused per-row attention, slow but correct.
// ---------------------------------------------------------------------------
__global__ __launch_bounds__(256) void fused_ctx_kernel(const float* __restrict__ Q,
                                                        const float* __restrict__ K,
                                                        const float* __restrict__ V,
                                                        float* __restrict__ O) {
    __shared__ float q[DD];
    __shared__ float s[LL];
    __shared__ float wred[8];
    __shared__ float bcast;

    const int bh = blockIdx.y;
    const int qi = blockIdx.x;
    const float* Qb = Q + ((size_t)bh * LL + qi) * DD;
    const float* Kb = K + (size_t)bh * LL * DD;
    const float* Vb = V + (size_t)bh * LL * DD;
    float* Ob = O + ((size_t)bh * LL + qi) * DD;

    const int tid = threadIdx.x;
    const int warp = tid >> 5, lane = tid & 31;
    if (tid < DD) q[tid] = Qb[tid];
    __syncthreads();

    float m = -CUDART_INF_F;
    for (int j = tid; j < LL; j += 256) {
        float d = 0.f;
#pragma unroll
        for (int d0 = 0; d0 < DD; d0++) d = fmaf(q[d0], Kb[(size_t)j * DD + d0], d);
        s[j] = d;
        m = fmaxf(m, d);
    }
#pragma unroll
    for (int o = 16; o > 0; o >>= 1) m = fmaxf(m, __shfl_xor_sync(0xffffffffu, m, o));
    if (lane == 0) wred[warp] = m;
    __syncthreads();
    if (warp == 0) {
        float x = (lane < 8) ? wred[lane] : -CUDART_INF_F;
#pragma unroll
        for (int o = 4; o > 0; o >>= 1) x = fmaxf(x, __shfl_xor_sync(0xffffffffu, x, o));
        if (lane == 0) bcast = x;
    }
    __syncthreads();
    m = bcast;

    float ssum = 0.f;
    for (int j = tid; j < LL; j += 256) {
        float e = __expf(s[j] - m);
        s[j] = e;
        ssum += e;
    }
#pragma unroll
    for (int o = 16; o > 0; o >>= 1) ssum += __shfl_xor_sync(0xffffffffu, ssum, o);
    __syncthreads();
    if (lane == 0) wred[warp] = ssum;
    __syncthreads();
    if (warp == 0) {
        float x = (lane < 8) ? wred[lane] : 0.f;
#pragma unroll
        for (int o = 4; o > 0; o >>= 1) x += __shfl_xor_sync(0xffffffffu, x, o);
        if (lane == 0) bcast = 1.f / x;
    }
    __syncthreads();
    const float inv = bcast;

    if (tid < DD) {
        float a = 0.f;
        for (int j = 0; j < LL; j++) a = fmaf(s[j], Vb[(size_t)j * DD + tid], a);
        Ob[tid] = a * inv;
    }
}

// ---------------------------------------------------------------------------
extern "C" void kernel_launch(void* const* d_in, const int* in_sizes, int n_in,
                              void* d_out, int out_size) {
    const float* Q = (const float*)d_in[0];
    const float* K = (const float*)d_in[1];
    const float* V = (const float*)d_in[2];
    float* out = (float*)d_out;

    if ((size_t)out_size >= CTX_ELEMS + ATT_ELEMS) {
        // Tuple output: context first, then attn.
        float* ctx = out;
        float* att = out + CTX_ELEMS;
        qk_kernel<<<dim3(16, 16, BHN), 256>>>(Q, K, att);
        softmax_kernel<<<BHN * LL, 256>>>(att);
        pv_kernel<<<dim3(1, 16, BHN), 256>>>(att, V, ctx);
    } else if ((size_t)out_size == ATT_ELEMS) {
        // attn only
        qk_kernel<<<dim3(16, 16, BHN), 256>>>(Q, K, out);
        softmax_kernel<<<BHN * LL, 256>>>(out);
    } else {
        // context only: fused fallback
        fused_ctx_kernel<<<dim3(LL, BHN), 256>>>(Q, K, V, out);
    }
}